// round 12
// baseline (speedup 1.0000x reference)
#include <cuda_runtime.h>
#include <cuda_bf16.h>

// MotionPrimitiveDecoder: logits[b,n,t,a] = dot(df[b,n,t,a,:], z[b,n,:]) + cd[t,a] - mean_fa(cd[t,:])
// where cd = ctx_features . u_ctx_w.  The frenet/polyline projection term is constant
// across (t,a) for fixed (b,n) and cancels exactly in u - u_mean, so
// map_polylines / idx / pts are never read.
//
// Shapes: B=32, N=64, T=40, A=6, Z=64, C=3.
//
// R12: R10 base (128-thr CTAs, warp-autonomous, rolling 5-deep pipeline) +
//      smem-staged coalesced output: per-slot results stored to a warp-private
//      smem region (no CTA barrier, __syncwarp only), final single ~120B
//      coalesced store per warp. Removes per-slot bias shuffle + 2 scattered
//      4B STGs per slot (~4x write-sector efficiency).

#define B_DIM 32
#define N_DIM 64
#define T_DIM 40
#define A_DIM 6
#define Z_DIM 64
#define TA_DIM (T_DIM * A_DIM)   // 240
#define ROWS_PER_WARP 30         // 5 t-groups of 6 actions
#define DEPTH 5
#define FULL 0xFFFFFFFFu

__global__ __launch_bounds__(128) void mpd_kernel(
    const float* __restrict__ z,     // [BN,Z]
    const float* __restrict__ df,    // [BN,TA,Z]
    const float* __restrict__ ctx,   // [BN,TA,3]
    const int*   __restrict__ fa,    // [BN,TA]
    const float* __restrict__ w,     // [3]
    float* __restrict__ out)         // [BN,TA]
{
    __shared__ float stage[4 * ROWS_PER_WARP];   // warp-private 30-float regions

    const int blk  = blockIdx.x;             // 0 .. 2*BN-1
    const int bn   = blk >> 1;
    const int hblk = blk & 1;                // which half of the 240 rows
    const int tid  = threadIdx.x;
    const int warp = tid >> 5;               // 0..3
    const int lane = tid & 31;
    const int half = lane >> 4;              // row parity within the warp's pair
    const int hl   = lane & 15;              // float4 index within the row

    const long dfb = (long)bn * TA_DIM * Z_DIM;
    const long fb  = (long)bn * TA_DIM;
    const int  R0  = hblk * (4 * ROWS_PER_WARP) + warp * ROWS_PER_WARP;

    // df pointer: slot j covers rows R0 + 2j + half, each row = 16 float4
    const float4* dfp = (const float4*)(df + dfb) + ((long)(R0 + half) * 16 + hl);

    // ---- prime DEPTH streaming loads first: DRAM busy from cycle 0,
    //      the entire bias phase below runs in their shadow ----
    float4 v[DEPTH];
    #pragma unroll
    for (int j = 0; j < DEPTH; j++) v[j] = dfp[(long)j * 32];   // +2 rows per slot

    // z directly from gmem (256B per bn, broadcast across half-warps / warps)
    const float4 zv = ((const float4*)(z + (long)bn * Z_DIM))[hl];

    // ---- warp-local bias: lane l (<30) owns row R0+l ----
    const float w0 = __ldg(w), w1 = __ldg(w + 1), w2 = __ldg(w + 2);

    const int lrow = (lane < ROWS_PER_WARP) ? lane : (ROWS_PER_WARP - 1);
    const float* c = ctx + ((long)(fb + R0 + lrow)) * 3;
    const float cd = c[0] * w0 + c[1] * w1 + c[2] * w2;
    const int   f  = fa[fb + R0 + lrow];

    // group of 6 lanes = one t; segmented masked mean via shuffles
    const int gbase = (lrow / A_DIM) * A_DIM;
    float s_all = 0.f, s_f = 0.f;
    int cnt = 0;
    #pragma unroll
    for (int k = 0; k < A_DIM; k++) {
        const float cdk = __shfl_sync(FULL, cd, gbase + k);
        const int   fk  = __shfl_sync(FULL, f,  gbase + k);
        s_all += cdk;
        if (fk) { s_f += cdk; cnt++; }
    }
    const float mean = cnt ? (s_f / (float)cnt) : (s_all / (float)A_DIM);
    const float bias = cd - mean;            // valid for lanes 0..29 (lane-indexed by row)

    // ---- streaming: rolling pipeline; results staged to warp-private smem ----
    float* st = stage + warp * ROWS_PER_WARP;

    #pragma unroll
    for (int j = 0; j < 15; j++) {
        const float4 x = v[j % DEPTH];

        if (j + DEPTH < 15) {
            v[j % DEPTH] = dfp[(long)(j + DEPTH) * 32];
        }

        float p = x.x * zv.x + x.y * zv.y + x.z * zv.z + x.w * zv.w;
        p += __shfl_xor_sync(FULL, p, 1);
        p += __shfl_xor_sync(FULL, p, 2);
        p += __shfl_xor_sync(FULL, p, 4);
        p += __shfl_xor_sync(FULL, p, 8);

        if (hl == 0) st[2 * j + half] = p;   // 4B STS, conflict-free
    }

    // ---- coalesced epilogue: one ~120B store per warp ----
    __syncwarp(FULL);
    if (lane < ROWS_PER_WARP) {
        out[fb + R0 + lane] = st[lane] + bias;
    }
}

extern "C" void kernel_launch(void* const* d_in, const int* in_sizes, int n_in,
                              void* d_out, int out_size) {
    // metadata order: map_polylines, idx, pts, z, decision_features,
    //                 ctx_features, feasible_actions, u_ctx_w, u_ctx_b
    const float* z   = (const float*)d_in[3];
    const float* df  = (const float*)d_in[4];
    const float* ctx = (const float*)d_in[5];
    const int*   fa  = (const int*)d_in[6];
    const float* w   = (const float*)d_in[7];
    float* out = (float*)d_out;

    mpd_kernel<<<2 * B_DIM * N_DIM, 128>>>(z, df, ctx, fa, w, out);
}

// round 16
// speedup vs baseline: 1.1333x; 1.1333x over previous
#include <cuda_runtime.h>
#include <cuda_bf16.h>

// MotionPrimitiveDecoder: logits[b,n,t,a] = dot(df[b,n,t,a,:], z[b,n,:]) + cd[t,a] - mean_fa(cd[t,:])
// where cd = ctx_features . u_ctx_w.  The frenet/polyline projection term is constant
// across (t,a) for fixed (b,n) and cancels exactly in u - u_mean, so
// map_polylines / idx / pts are never read.
//
// Shapes: B=32, N=64, T=40, A=6, Z=64, C=3.
//
// R13 (consolidated best): R9 warp-autonomous kernel (no smem, no __syncthreads,
//     rolling 5-deep pipeline, half-warp per row) + __stcs evict-first output
//     stores + bias shuffle hoisted off the reduction critical path.
//     Kernel runs within ~2% of the achieved-DRAM-bandwidth floor
//     (136 MB @ ~5.5 TB/s); all scheduling/occupancy/depth levers verified flat.

#define B_DIM 32
#define N_DIM 64
#define T_DIM 40
#define A_DIM 6
#define Z_DIM 64
#define TA_DIM (T_DIM * A_DIM)   // 240
#define ROWS_PER_WARP 30         // 5 t-groups of 6 actions
#define DEPTH 5
#define FULL 0xFFFFFFFFu

__global__ __launch_bounds__(256) void mpd_kernel(
    const float* __restrict__ z,     // [BN,Z]
    const float* __restrict__ df,    // [BN,TA,Z]
    const float* __restrict__ ctx,   // [BN,TA,3]
    const int*   __restrict__ fa,    // [BN,TA]
    const float* __restrict__ w,     // [3]
    float* __restrict__ out)         // [BN,TA]
{
    const int bn   = blockIdx.x;             // 0 .. B*N-1
    const int tid  = threadIdx.x;
    const int warp = tid >> 5;
    const int lane = tid & 31;
    const int half = lane >> 4;              // row parity within the warp's pair
    const int hl   = lane & 15;              // float4 index within the row

    const long dfb = (long)bn * TA_DIM * Z_DIM;
    const long fb  = (long)bn * TA_DIM;
    const int  R0  = warp * ROWS_PER_WARP;   // first row owned by this warp

    // df pointer: slot j covers rows R0 + 2j + half, each row = 16 float4
    const float4* dfp = (const float4*)(df + dfb) + ((long)(R0 + half) * 16 + hl);

    // ---- prime DEPTH streaming loads first: DRAM busy from cycle 0,
    //      the entire bias phase below runs in their shadow ----
    float4 v[DEPTH];
    #pragma unroll
    for (int j = 0; j < DEPTH; j++) v[j] = dfp[(long)j * 32];   // +2 rows per slot

    // z directly from gmem (256B per bn, broadcast across half-warps / warps)
    const float4 zv = ((const float4*)(z + (long)bn * Z_DIM))[hl];

    // ---- warp-local bias: lane l (<30) owns row R0+l ----
    const float w0 = __ldg(w), w1 = __ldg(w + 1), w2 = __ldg(w + 2);

    const int lrow = (lane < ROWS_PER_WARP) ? lane : (ROWS_PER_WARP - 1);
    const float* c = ctx + ((long)(fb + R0 + lrow)) * 3;
    const float cd = c[0] * w0 + c[1] * w1 + c[2] * w2;
    const int   f  = fa[fb + R0 + lrow];

    // group of 6 lanes = one t; segmented masked mean via shuffles
    const int gbase = (lrow / A_DIM) * A_DIM;
    float s_all = 0.f, s_f = 0.f;
    int cnt = 0;
    #pragma unroll
    for (int k = 0; k < A_DIM; k++) {
        const float cdk = __shfl_sync(FULL, cd, gbase + k);
        const int   fk  = __shfl_sync(FULL, f,  gbase + k);
        s_all += cdk;
        if (fk) { s_f += cdk; cnt++; }
    }
    const float mean = cnt ? (s_f / (float)cnt) : (s_all / (float)A_DIM);
    const float bias = cd - mean;            // valid for lanes 0..29 (lane-indexed by row)

    // ---- streaming: rolling pipeline, reduce slot j, refill slot j+DEPTH ----
    #pragma unroll
    for (int j = 0; j < 15; j++) {
        // bias broadcast first: off the load/reduction critical path
        const float bb = __shfl_sync(FULL, bias, 2 * j + half);

        const float4 x = v[j % DEPTH];

        if (j + DEPTH < 15) {
            v[j % DEPTH] = dfp[(long)(j + DEPTH) * 32];
        }

        float p = x.x * zv.x + x.y * zv.y + x.z * zv.z + x.w * zv.w;
        p += __shfl_xor_sync(FULL, p, 1);
        p += __shfl_xor_sync(FULL, p, 2);
        p += __shfl_xor_sync(FULL, p, 4);
        p += __shfl_xor_sync(FULL, p, 8);

        if (hl == 0) {
            __stcs(&out[fb + R0 + 2 * j + half], p + bb);   // evict-first write
        }
    }
}

extern "C" void kernel_launch(void* const* d_in, const int* in_sizes, int n_in,
                              void* d_out, int out_size) {
    // metadata order: map_polylines, idx, pts, z, decision_features,
    //                 ctx_features, feasible_actions, u_ctx_w, u_ctx_b
    const float* z   = (const float*)d_in[3];
    const float* df  = (const float*)d_in[4];
    const float* ctx = (const float*)d_in[5];
    const int*   fa  = (const int*)d_in[6];
    const float* w   = (const float*)d_in[7];
    float* out = (float*)d_out;

    mpd_kernel<<<B_DIM * N_DIM, 256>>>(z, df, ctx, fa, w, out);
}

// round 17
// speedup vs baseline: 1.2134x; 1.0707x over previous
#include <cuda_runtime.h>
#include <cuda_bf16.h>

// MotionPrimitiveDecoder: logits[b,n,t,a] = dot(df[b,n,t,a,:], z[b,n,:]) + cd[t,a] - mean_fa(cd[t,:])
// where cd = ctx_features . u_ctx_w.  The frenet/polyline projection term is constant
// across (t,a) for fixed (b,n) and cancels exactly in u - u_mean, so
// map_polylines / idx / pts are never read.
//
// Shapes: B=32, N=64, T=40, A=6, Z=64, C=3.
//
// R17: R13 base (warp-autonomous, rolling 5-deep pipeline, __stcs output) +
//      __ldcg on df streaming loads: df is read exactly once (125.8 MB, zero
//      reuse) so L1 allocation for it is pure churn; cache at L2 only.

#define B_DIM 32
#define N_DIM 64
#define T_DIM 40
#define A_DIM 6
#define Z_DIM 64
#define TA_DIM (T_DIM * A_DIM)   // 240
#define ROWS_PER_WARP 30         // 5 t-groups of 6 actions
#define DEPTH 5
#define FULL 0xFFFFFFFFu

__global__ __launch_bounds__(256) void mpd_kernel(
    const float* __restrict__ z,     // [BN,Z]
    const float* __restrict__ df,    // [BN,TA,Z]
    const float* __restrict__ ctx,   // [BN,TA,3]
    const int*   __restrict__ fa,    // [BN,TA]
    const float* __restrict__ w,     // [3]
    float* __restrict__ out)         // [BN,TA]
{
    const int bn   = blockIdx.x;             // 0 .. B*N-1
    const int tid  = threadIdx.x;
    const int warp = tid >> 5;
    const int lane = tid & 31;
    const int half = lane >> 4;              // row parity within the warp's pair
    const int hl   = lane & 15;              // float4 index within the row

    const long dfb = (long)bn * TA_DIM * Z_DIM;
    const long fb  = (long)bn * TA_DIM;
    const int  R0  = warp * ROWS_PER_WARP;   // first row owned by this warp

    // df pointer: slot j covers rows R0 + 2j + half, each row = 16 float4
    const float4* dfp = (const float4*)(df + dfb) + ((long)(R0 + half) * 16 + hl);

    // ---- prime DEPTH streaming loads first: DRAM busy from cycle 0,
    //      the entire bias phase below runs in their shadow.
    //      __ldcg: L2-only, df has zero reuse -> skip L1 allocation churn. ----
    float4 v[DEPTH];
    #pragma unroll
    for (int j = 0; j < DEPTH; j++) v[j] = __ldcg(dfp + (long)j * 32);

    // z directly from gmem (256B per bn, broadcast across half-warps / warps)
    const float4 zv = ((const float4*)(z + (long)bn * Z_DIM))[hl];

    // ---- warp-local bias: lane l (<30) owns row R0+l ----
    const float w0 = __ldg(w), w1 = __ldg(w + 1), w2 = __ldg(w + 2);

    const int lrow = (lane < ROWS_PER_WARP) ? lane : (ROWS_PER_WARP - 1);
    const float* c = ctx + ((long)(fb + R0 + lrow)) * 3;
    const float cd = c[0] * w0 + c[1] * w1 + c[2] * w2;
    const int   f  = fa[fb + R0 + lrow];

    // group of 6 lanes = one t; segmented masked mean via shuffles
    const int gbase = (lrow / A_DIM) * A_DIM;
    float s_all = 0.f, s_f = 0.f;
    int cnt = 0;
    #pragma unroll
    for (int k = 0; k < A_DIM; k++) {
        const float cdk = __shfl_sync(FULL, cd, gbase + k);
        const int   fk  = __shfl_sync(FULL, f,  gbase + k);
        s_all += cdk;
        if (fk) { s_f += cdk; cnt++; }
    }
    const float mean = cnt ? (s_f / (float)cnt) : (s_all / (float)A_DIM);
    const float bias = cd - mean;            // valid for lanes 0..29 (lane-indexed by row)

    // ---- streaming: rolling pipeline, reduce slot j, refill slot j+DEPTH ----
    #pragma unroll
    for (int j = 0; j < 15; j++) {
        // bias broadcast first: off the load/reduction critical path
        const float bb = __shfl_sync(FULL, bias, 2 * j + half);

        const float4 x = v[j % DEPTH];

        if (j + DEPTH < 15) {
            v[j % DEPTH] = __ldcg(dfp + (long)(j + DEPTH) * 32);
        }

        float p = x.x * zv.x + x.y * zv.y + x.z * zv.z + x.w * zv.w;
        p += __shfl_xor_sync(FULL, p, 1);
        p += __shfl_xor_sync(FULL, p, 2);
        p += __shfl_xor_sync(FULL, p, 4);
        p += __shfl_xor_sync(FULL, p, 8);

        if (hl == 0) {
            __stcs(&out[fb + R0 + 2 * j + half], p + bb);   // evict-first write
        }
    }
}

extern "C" void kernel_launch(void* const* d_in, const int* in_sizes, int n_in,
                              void* d_out, int out_size) {
    // metadata order: map_polylines, idx, pts, z, decision_features,
    //                 ctx_features, feasible_actions, u_ctx_w, u_ctx_b
    const float* z   = (const float*)d_in[3];
    const float* df  = (const float*)d_in[4];
    const float* ctx = (const float*)d_in[5];
    const int*   fa  = (const int*)d_in[6];
    const float* w   = (const float*)d_in[7];
    float* out = (float*)d_out;

    mpd_kernel<<<B_DIM * N_DIM, 256>>>(z, df, ctx, fa, w, out);
}